// round 1
// baseline (speedup 1.0000x reference)
#include <cuda_runtime.h>

// Cost volume: out[b,k,h,w] = (1/81) * sum_c x1[b,c,h,w] * x2[b,c,h-i,w-j]
//   i,j in [-4,4], k = (9i+j) mod 81. Zero padding outside image bounds.
// Shapes: B=4, C=128, H=128, W=256, D=81. fp32.

#define Bn 4
#define Cn 128
#define Hn 128
#define Wn 256
#define Dn 81
#define TH 8
#define TW 32
#define CC 8          // channels per smem chunk
#define NTHR 128

__global__ __launch_bounds__(NTHR, 1)
void costvol_kernel(const float* __restrict__ x1,
                    const float* __restrict__ x2,
                    float* __restrict__ out) {
    __shared__ float s1[CC][TH][TW];          // 8*8*32*4  =  8 KB
    __shared__ float s2[CC][TH + 8][TW + 8];  // 8*16*40*4 = 20 KB

    const int w0 = blockIdx.x * TW;   // gridDim.x = W/TW = 8
    const int h0 = blockIdx.y * TH;   // gridDim.y = H/TH = 16
    const int b  = blockIdx.z;        // gridDim.z = B    = 4

    const int tid = threadIdx.x;
    const int tx  = tid & 15;         // 16 column-pair groups (covers 32 w)
    const int ty  = tid >> 4;         // 8 rows

    float acc0[81], acc1[81];
#pragma unroll
    for (int k = 0; k < 81; k++) { acc0[k] = 0.f; acc1[k] = 0.f; }

    for (int c0 = 0; c0 < Cn; c0 += CC) {
        // ---- load x1 chunk: CC*TH*TW/4 = 512 float4, 4 per thread ----
#pragma unroll
        for (int q = 0; q < 4; q++) {
            int f   = tid + q * NTHR;        // 0..511
            int cc  = f >> 6;                // 64 float4 per channel
            int rem = f & 63;
            int hh  = rem >> 3;              // 8 float4 per row
            int k4  = rem & 7;
            const float4 v = *(const float4*)(x1 +
                (((size_t)((b * Cn + c0 + cc) * Hn + h0 + hh)) * Wn + w0 + 4 * k4));
            *(float4*)&s1[cc][hh][4 * k4] = v;
        }
        // ---- load x2 chunk (with +-4 halo): CC*16*10 = 1280 float4, 10/thread ----
#pragma unroll
        for (int q = 0; q < 10; q++) {
            int f   = tid + q * NTHR;        // 0..1279
            int cc  = f / 160;               // 16 rows * 10 float4
            int rem = f - cc * 160;
            int hh  = rem / 10;
            int k4  = rem - hh * 10;
            int hg  = h0 - 4 + hh;
            int wg  = w0 - 4 + 4 * k4;       // float4-aligned by construction
            float4 v = make_float4(0.f, 0.f, 0.f, 0.f);
            if ((unsigned)hg < (unsigned)Hn && (unsigned)wg < (unsigned)Wn)
                v = *(const float4*)(x2 +
                    (((size_t)((b * Cn + c0 + cc) * Hn + hg)) * Wn + wg));
            *(float4*)&s2[cc][hh][4 * k4] = v;
        }
        __syncthreads();

        // ---- compute: per channel, 9 i-shifts, 10-float register window, 9 j ----
#pragma unroll 2
        for (int cc = 0; cc < CC; cc++) {
            const float a0 = s1[cc][ty][2 * tx];
            const float a1 = s1[cc][ty][2 * tx + 1];
#pragma unroll
            for (int ii = 0; ii < 9; ii++) {
                // x2 row for shift di=ii-4: hh = ty + 8 - ii  (in [ty, ty+8])
                const float* row = &s2[cc][ty + 8 - ii][2 * tx];
                float wnd[10];
#pragma unroll
                for (int m = 0; m < 10; m += 2) {
                    float2 t = *(const float2*)(row + m);  // 8B-aligned LDS.64
                    wnd[m] = t.x; wnd[m + 1] = t.y;
                }
#pragma unroll
                for (int jj = 0; jj < 9; jj++) {
                    // pixel0 reads window idx 8-jj, pixel1 reads 9-jj
                    acc0[ii * 9 + jj] += a0 * wnd[8 - jj];
                    acc1[ii * 9 + jj] += a1 * wnd[9 - jj];
                }
            }
        }
        __syncthreads();
    }

    // ---- epilogue: k = (9*(ii-4) + (jj-4)) mod 81 = (9*ii + jj + 41) % 81 ----
    const float inv = 1.0f / 81.0f;
    const int hg = h0 + ty;
    const int wg = w0 + 2 * tx;
#pragma unroll
    for (int ii = 0; ii < 9; ii++) {
#pragma unroll
        for (int jj = 0; jj < 9; jj++) {
            int k = (9 * ii + jj + 41) % 81;
            float2 v = make_float2(acc0[ii * 9 + jj] * inv,
                                   acc1[ii * 9 + jj] * inv);
            *(float2*)(out + (((size_t)((b * Dn + k) * Hn + hg)) * Wn + wg)) = v;
        }
    }
}

extern "C" void kernel_launch(void* const* d_in, const int* in_sizes, int n_in,
                              void* d_out, int out_size) {
    (void)in_sizes; (void)n_in; (void)out_size;
    const float* x1 = (const float*)d_in[0];
    const float* x2 = (const float*)d_in[1];
    float* out = (float*)d_out;
    dim3 grid(Wn / TW, Hn / TH, Bn);   // (8, 16, 4) = 512 blocks
    costvol_kernel<<<grid, NTHR>>>(x1, x2, out);
}